// round 5
// baseline (speedup 1.0000x reference)
#include <cuda_runtime.h>

// Shapes: B_T=32,N=2048,E=8192,D=128,T=8,H=8,dh=16,B=4
// q rows 65536, k/v rows 262144 (edge branch only; x_0 branch is dead code:
// the reference recomputes out from q each loop iteration).

__device__ float g_q[65536 * 128];     // q (softmax+rope), then attn output in place
__device__ float g_WT[4 * 16384];      // WqT, Wk1T, Wv1T, WoT ; WT[k*128+c] = W[c*128+k]
__device__ float g_part[4096 * 272];   // per-block partials: 256 kv + 16 ksum
__device__ float g_kv[32 * 272];       // reduced per (b,h)

#define LDW 132            // padded W row (floats)
#define LDXT 72            // padded XsT row (floats)
#define SM_X (128 * LDXT)  // 9216 floats
#define SM_W (128 * LDW)   // 16896 floats

// XsT[k*LDXT + r] = X[g0+r][k]
static __device__ __forceinline__ void load_X_T(float* XsT, const float* __restrict__ X,
                                                int g0, int tid) {
#pragma unroll
    for (int rep = 0; rep < 8; ++rep) {
        int i4 = tid + rep * 256, r = i4 >> 5, c4 = i4 & 31;
        float4 v = *(const float4*)(X + (size_t)(g0 + r) * 128 + c4 * 4);
        XsT[(c4 * 4 + 0) * LDXT + r] = v.x;
        XsT[(c4 * 4 + 1) * LDXT + r] = v.y;
        XsT[(c4 * 4 + 2) * LDXT + r] = v.z;
        XsT[(c4 * 4 + 3) * LDXT + r] = v.w;
    }
}
static __device__ __forceinline__ void load_W(float* Ws, const float* __restrict__ src, int tid) {
#pragma unroll
    for (int rep = 0; rep < 16; ++rep) {
        int i4 = tid + rep * 256, k = i4 >> 5, c4 = i4 & 31;
        *(float4*)(Ws + k * LDW + c4 * 4) = *(const float4*)(src + k * 128 + c4 * 4);
    }
}

// 256 thr: warp cg=tid>>5 -> cols [cg*16,+16); lane -> rows {lane, lane+32}
static __device__ __forceinline__ void gemm_main(const float* XsT, const float* Ws,
                                                 int lane, int cg, float acc[2][16]) {
#pragma unroll
    for (int i = 0; i < 2; ++i)
#pragma unroll
        for (int e = 0; e < 16; ++e) acc[i][e] = 0.f;
#pragma unroll 2
    for (int k = 0; k < 128; ++k) {
        float x0 = XsT[k * LDXT + lane];
        float x1 = XsT[k * LDXT + lane + 32];
        const float4* w = (const float4*)(Ws + k * LDW + cg * 16);
#pragma unroll
        for (int p = 0; p < 4; ++p) {
            float4 wv = w[p];
            acc[0][4 * p + 0] += x0 * wv.x; acc[0][4 * p + 1] += x0 * wv.y;
            acc[0][4 * p + 2] += x0 * wv.z; acc[0][4 * p + 3] += x0 * wv.w;
            acc[1][4 * p + 0] += x1 * wv.x; acc[1][4 * p + 1] += x1 * wv.y;
            acc[1][4 * p + 2] += x1 * wv.z; acc[1][4 * p + 3] += x1 * wv.w;
        }
    }
}

static __device__ __forceinline__ void addbias(const float acc[16], const float* __restrict__ bias,
                                               int cg, float v[16]) {
#pragma unroll
    for (int e = 0; e < 16; ++e) v[e] = acc[e] + bias[cg * 16 + e];
}
static __device__ __forceinline__ void softmax16(float v[16]) {
    float m = v[0];
#pragma unroll
    for (int e = 1; e < 16; ++e) m = fmaxf(m, v[e]);
    float s = 0.f;
#pragma unroll
    for (int e = 0; e < 16; ++e) { v[e] = __expf(v[e] - m); s += v[e]; }
    float inv = 1.0f / s;
#pragma unroll
    for (int e = 0; e < 16; ++e) v[e] *= inv;
}
static __device__ __forceinline__ void rope16(float v[16], float t) {
    const float F[8] = {1.0f, 0.31622776601683794f, 0.1f, 0.031622776601683794f,
                        0.01f, 0.0031622776601683794f, 0.001f, 0.00031622776601683794f};
#pragma unroll
    for (int p = 0; p < 8; ++p) {
        float sn, cs; __sincosf(t * F[p], &sn, &cs);
        float a = v[2 * p], b = v[2 * p + 1];
        v[2 * p] = a * cs - b * sn;
        v[2 * p + 1] = a * sn + b * cs;
    }
}
static __device__ __forceinline__ void store16(float* p, const float v[16]) {
#pragma unroll
    for (int q = 0; q < 4; ++q)
        *(float4*)(p + 4 * q) = make_float4(v[4 * q], v[4 * q + 1], v[4 * q + 2], v[4 * q + 3]);
}

__global__ void k_wtrans(const float* __restrict__ w0, const float* __restrict__ w1,
                         const float* __restrict__ w2, const float* __restrict__ w3) {
    const float* s = blockIdx.x == 0 ? w0 : blockIdx.x == 1 ? w1 : blockIdx.x == 2 ? w2 : w3;
    float* d = g_WT + blockIdx.x * 16384;
    for (int i = threadIdx.x; i < 16384; i += 256) d[i] = s[(i & 127) * 128 + (i >> 7)];
}

// q = rope(softmax(q_data@WqT+bq))   rope-t = (g>>8)&7
__global__ void __launch_bounds__(256, 2) k_qproj(const float* __restrict__ X,
                                                  const float* __restrict__ bias) {
    extern __shared__ float sm[];
    float* XsT = sm; float* Ws = sm + SM_X;
    int tid = threadIdx.x, lane = tid & 31, cg = tid >> 5, g0 = blockIdx.x * 64;
    load_X_T(XsT, X, g0, tid);
    load_W(Ws, g_WT, tid);
    __syncthreads();
    float acc[2][16];
    gemm_main(XsT, Ws, lane, cg, acc);
#pragma unroll
    for (int i = 0; i < 2; ++i) {
        int g = g0 + lane + 32 * i;
        float v[16];
        addbias(acc[i], bias, cg, v);
        softmax16(v);
        rope16(v, (float)((g >> 8) & 7));
        store16(g_q + (size_t)g * 128 + cg * 16, v);
    }
}

// fused K/V projection + softmax(rope(k)) + block-local kv/ksum reduction
__global__ void __launch_bounds__(256, 1) k_kv(const float* __restrict__ X,
                                               const float* __restrict__ bk,
                                               const float* __restrict__ bv) {
    extern __shared__ float sm[];
    float* XsT = sm;
    float* Wk = sm + SM_X;          // later reused as ks[512][17]
    float* Wv = Wk + SM_W;          // later reused as vs[512][18]
    float* ks = Wk;
    float* vs = Wv;
    int tid = threadIdx.x, lane = tid & 31, cg = tid >> 5, g0 = blockIdx.x * 64;
    load_X_T(XsT, X, g0, tid);
    load_W(Wk, g_WT + 16384, tid);
    load_W(Wv, g_WT + 32768, tid);
    __syncthreads();

    float acc[2][16];
    gemm_main(XsT, Wk, lane, cg, acc);
    float t = (float)((g0 >> 10) & 7);
    float kc[2][16];
#pragma unroll
    for (int i = 0; i < 2; ++i) {
        addbias(acc[i], bk, cg, kc[i]);
        rope16(kc[i], t);
        softmax16(kc[i]);
    }
    gemm_main(XsT, Wv, lane, cg, acc);   // acc = v (no bias yet)
    __syncthreads();                     // all gemm reads of Wk/Wv done
#pragma unroll
    for (int i = 0; i < 2; ++i) {
        int s = (lane + 32 * i) * 8 + cg;
#pragma unroll
        for (int e = 0; e < 16; ++e) {
            ks[s * 17 + e] = kc[i][e];
            vs[s * 18 + e] = acc[i][e] + bv[cg * 16 + e];
        }
    }
    __syncthreads();

    // one thread per (d, e): kv[d][e] = sum_s k[s][d] * v[s][e]
    int d = tid & 15, e = tid >> 4;
    float kv = 0.f, sk = 0.f;
#pragma unroll 4
    for (int s = 0; s < 512; ++s) {
        float kd = ks[s * 17 + d];
        kv += kd * vs[s * 18 + e];
        if (e == 0) sk += kd;
    }
    float* out = g_part + (size_t)blockIdx.x * 272;
    out[d * 16 + e] = kv;
    if (e == 0) out[256 + d] = sk;
}

__global__ void k_kvreduce() {
    int bh = blockIdx.x, t = threadIdx.x;
    float s = 0.f;
    for (int i = 0; i < 128; ++i) s += g_part[(size_t)(bh * 128 + i) * 272 + t];
    g_kv[bh * 272 + t] = s;
}

// out = q + (q@kv)*Dinv, per 16-chunk, in place in g_q
__global__ void __launch_bounds__(256, 4) k_attn() {
    __shared__ __align__(16) float kv[272];
    int tid = threadIdx.x, g0 = blockIdx.x * 64, bh = g0 >> 11;
    for (int i = tid; i < 272; i += 256) kv[i] = g_kv[bh * 272 + i];   // FIX: full 272 loaded
    __syncthreads();
#pragma unroll
    for (int it = 0; it < 2; ++it) {
        int cc = tid + 256 * it, row = cc >> 3, j = cc & 7;
        float* qp = g_q + (size_t)(g0 + row) * 128 + j * 16;
        float q[16];
#pragma unroll
        for (int p = 0; p < 4; ++p) {
            float4 x = *(const float4*)(qp + 4 * p);
            q[4 * p] = x.x; q[4 * p + 1] = x.y; q[4 * p + 2] = x.z; q[4 * p + 3] = x.w;
        }
        float den = 0.f;
#pragma unroll
        for (int d = 0; d < 16; ++d) den += q[d] * kv[256 + d];
        float Dinv = 1.0f / fmaxf(den, 1e-8f);
        float o[16];
#pragma unroll
        for (int e = 0; e < 16; ++e) o[e] = 0.f;
#pragma unroll
        for (int d = 0; d < 16; ++d) {
            float qd = q[d];
            const float* kr = kv + d * 16;
#pragma unroll
            for (int e = 0; e < 16; ++e) o[e] += qd * kr[e];
        }
        float r[16];
#pragma unroll
        for (int e = 0; e < 16; ++e) r[e] = q[e] + o[e] * Dinv;
        store16(qp, r);
    }
}

// final: gather (head transpose) @ WoT + bo -> d_out (flat layout matches)
__global__ void __launch_bounds__(256, 2) k_out(const float* __restrict__ bias,
                                                float* __restrict__ out) {
    extern __shared__ float sm[];
    float* XsT = sm; float* Ws = sm + SM_X;
    int tid = threadIdx.x, lane = tid & 31, cg = tid >> 5, g0 = blockIdx.x * 64;
#pragma unroll
    for (int rep = 0; rep < 8; ++rep) {
        int i4 = tid + rep * 256, r = i4 >> 5, c4 = i4 & 31;
        int m = g0 + r, s = m & 16383, base = m & ~16383;
        int src = base + (c4 >> 2) * 2048 + (s >> 3);
        float4 v = *(const float4*)(g_q + (size_t)src * 128 + (s & 7) * 16 + (c4 & 3) * 4);
        XsT[(c4 * 4 + 0) * LDXT + r] = v.x;
        XsT[(c4 * 4 + 1) * LDXT + r] = v.y;
        XsT[(c4 * 4 + 2) * LDXT + r] = v.z;
        XsT[(c4 * 4 + 3) * LDXT + r] = v.w;
    }
    load_W(Ws, g_WT + 49152, tid);
    __syncthreads();
    float acc[2][16];
    gemm_main(XsT, Ws, lane, cg, acc);
#pragma unroll
    for (int i = 0; i < 2; ++i) {
        int g = g0 + lane + 32 * i;
        float v[16];
        addbias(acc[i], bias, cg, v);
        store16(out + (size_t)g * 128 + cg * 16, v);
    }
}

extern "C" void kernel_launch(void* const* d_in, const int* in_sizes, int n_in,
                              void* d_out, int out_size) {
    const float* edge = (const float*)d_in[1];
    const float* qdat = (const float*)d_in[2];
    const float* Wq = (const float*)d_in[3];
    const float* bq = (const float*)d_in[4];
    const float* Wk1 = (const float*)d_in[9];
    const float* bk1 = (const float*)d_in[10];
    const float* Wv1 = (const float*)d_in[11];
    const float* bv1 = (const float*)d_in[12];
    const float* Wo = (const float*)d_in[13];
    const float* bo = (const float*)d_in[14];

    int smQ = (SM_X + SM_W) * 4;          // 104448
    int smKV = (SM_X + 2 * SM_W) * 4;     // 172032
    cudaFuncSetAttribute(k_qproj, cudaFuncAttributeMaxDynamicSharedMemorySize, smQ);
    cudaFuncSetAttribute(k_kv, cudaFuncAttributeMaxDynamicSharedMemorySize, smKV);
    cudaFuncSetAttribute(k_out, cudaFuncAttributeMaxDynamicSharedMemorySize, smQ);

    k_wtrans<<<4, 256>>>(Wq, Wk1, Wv1, Wo);
    k_qproj<<<1024, 256, smQ>>>(qdat, bq);
    k_kv<<<4096, 256, smKV>>>(edge, bk1, bv1);
    k_kvreduce<<<32, 272>>>();
    k_attn<<<1024, 256>>>();
    k_out<<<1024, 256, smQ>>>(bo, (float*)d_out);
}

// round 6
// speedup vs baseline: 2.0387x; 2.0387x over previous
#include <cuda_runtime.h>

typedef unsigned long long ull;
typedef unsigned int uint;

// Shapes: B_T=32,N=2048,E=8192,D=128,T=8,H=8,dh=16,B=4
// q rows 65536, k/v rows 262144 (edge branch only; x_0 branch is dead code).

__device__ float g_q[65536 * 128];     // q (softmax+rope), then attn output in place
__device__ float g_WT[4 * 16384];      // WqT, Wk1T, Wv1T, WoT ; WT[k*128+c]=W[c*128+k]
__device__ float g_part[4096 * 272];   // per-block kv partials (256 kv + 16 ksum)
__device__ float g_kv[32 * 272];       // reduced per (b,h)

static __device__ __forceinline__ ull bcast2(float x) {
    ull r; asm("mov.b64 %0, {%1, %1};" : "=l"(r) : "r"(__float_as_uint(x))); return r;
}
static __device__ __forceinline__ void ffma2(ull& a, ull x, ull y) {
    asm("fma.rn.f32x2 %0, %1, %2, %0;" : "+l"(a) : "l"(x), "l"(y));
}
static __device__ __forceinline__ void unpk2(ull v, float& lo, float& hi) {
    uint l, h; asm("mov.b64 {%0, %1}, %2;" : "=r"(l), "=r"(h) : "l"(v));
    lo = __uint_as_float(l); hi = __uint_as_float(h);
}

#define LDW 132            // padded W row (floats)
#define LDXT 72            // padded XsT row (floats)
#define SM_X (128 * LDXT)  // 9216 floats
#define SM_W (128 * LDW)   // 16896 floats

// XsT[k*LDXT + r] = X[g0+r][k]
static __device__ __forceinline__ void load_X_T(float* XsT, const float* __restrict__ X,
                                                int g0, int tid) {
#pragma unroll
    for (int rep = 0; rep < 8; ++rep) {
        int i4 = tid + rep * 256, r = i4 >> 5, c4 = i4 & 31;
        float4 v = *(const float4*)(X + (size_t)(g0 + r) * 128 + c4 * 4);
        XsT[(c4 * 4 + 0) * LDXT + r] = v.x;
        XsT[(c4 * 4 + 1) * LDXT + r] = v.y;
        XsT[(c4 * 4 + 2) * LDXT + r] = v.z;
        XsT[(c4 * 4 + 3) * LDXT + r] = v.w;
    }
}
static __device__ __forceinline__ void load_W(float* Ws, const float* __restrict__ src, int tid) {
#pragma unroll
    for (int rep = 0; rep < 16; ++rep) {
        int i4 = tid + rep * 256, k = i4 >> 5, c4 = i4 & 31;
        *(float4*)(Ws + k * LDW + c4 * 4) = *(const float4*)(src + k * 128 + c4 * 4);
    }
}

// 256 thr: warp cg=tid>>5 -> cols [cg*16,+16); lane -> rows {lane, lane+32}
// acc[i][p] packs cols (cg*16+2p, cg*16+2p+1) for row lane+32*i.
static __device__ __forceinline__ void gemm_main(const float* XsT, const float* Ws,
                                                 int lane, int cg, ull acc[2][8]) {
#pragma unroll
    for (int i = 0; i < 2; ++i)
#pragma unroll
        for (int p = 0; p < 8; ++p) acc[i][p] = 0ULL;
#pragma unroll 4
    for (int k = 0; k < 128; ++k) {
        ull x0 = bcast2(XsT[k * LDXT + lane]);
        ull x1 = bcast2(XsT[k * LDXT + lane + 32]);
        const ull* w = (const ull*)(Ws + k * LDW + cg * 16);
#pragma unroll
        for (int p = 0; p < 8; ++p) {
            ull wp = w[p];
            ffma2(acc[0][p], x0, wp);
            ffma2(acc[1][p], x1, wp);
        }
    }
}

static __device__ __forceinline__ void unpack16(const ull a[8], const float* __restrict__ bias,
                                                int cg, float v[16]) {
#pragma unroll
    for (int p = 0; p < 8; ++p) {
        float lo, hi; unpk2(a[p], lo, hi);
        v[2 * p] = lo + bias[cg * 16 + 2 * p];
        v[2 * p + 1] = hi + bias[cg * 16 + 2 * p + 1];
    }
}
static __device__ __forceinline__ void softmax16(float v[16]) {
    float m = v[0];
#pragma unroll
    for (int e = 1; e < 16; ++e) m = fmaxf(m, v[e]);
    float s = 0.f;
#pragma unroll
    for (int e = 0; e < 16; ++e) { v[e] = __expf(v[e] - m); s += v[e]; }
    float inv = 1.0f / s;
#pragma unroll
    for (int e = 0; e < 16; ++e) v[e] *= inv;
}
static __device__ __forceinline__ void rope16(float v[16], float t) {
    const float F[8] = {1.0f, 0.31622776601683794f, 0.1f, 0.031622776601683794f,
                        0.01f, 0.0031622776601683794f, 0.001f, 0.00031622776601683794f};
#pragma unroll
    for (int p = 0; p < 8; ++p) {
        float sn, cs; __sincosf(t * F[p], &sn, &cs);
        float a = v[2 * p], b = v[2 * p + 1];
        v[2 * p] = a * cs - b * sn;
        v[2 * p + 1] = a * sn + b * cs;
    }
}
static __device__ __forceinline__ void store16(float* p, const float v[16]) {
#pragma unroll
    for (int q = 0; q < 4; ++q)
        *(float4*)(p + 4 * q) = make_float4(v[4 * q], v[4 * q + 1], v[4 * q + 2], v[4 * q + 3]);
}

__global__ void k_wtrans(const float* __restrict__ w0, const float* __restrict__ w1,
                         const float* __restrict__ w2, const float* __restrict__ w3) {
    const float* s = blockIdx.x == 0 ? w0 : blockIdx.x == 1 ? w1 : blockIdx.x == 2 ? w2 : w3;
    float* d = g_WT + blockIdx.x * 16384;
    for (int i = threadIdx.x; i < 16384; i += 256) d[i] = s[(i & 127) * 128 + (i >> 7)];
}

// q = rope(softmax(q_data@WqT+bq))   rope-t = (g>>8)&7
__global__ void __launch_bounds__(256, 2) k_qproj(const float* __restrict__ X,
                                                  const float* __restrict__ bias) {
    extern __shared__ float sm[];
    float* XsT = sm; float* Ws = sm + SM_X;
    int tid = threadIdx.x, lane = tid & 31, cg = tid >> 5, g0 = blockIdx.x * 64;
    load_X_T(XsT, X, g0, tid);
    load_W(Ws, g_WT, tid);
    __syncthreads();
    ull acc[2][8];
    gemm_main(XsT, Ws, lane, cg, acc);
#pragma unroll
    for (int i = 0; i < 2; ++i) {
        int g = g0 + lane + 32 * i;
        float v[16];
        unpack16(acc[i], bias, cg, v);
        softmax16(v);
        rope16(v, (float)((g >> 8) & 7));
        store16(g_q + (size_t)g * 128 + cg * 16, v);
    }
}

// fused K/V projection + softmax(rope(k)) + block-local kv/ksum reduction
__global__ void __launch_bounds__(256, 1) k_kv(const float* __restrict__ X,
                                               const float* __restrict__ bk,
                                               const float* __restrict__ bv) {
    extern __shared__ float sm[];
    float* XsT = sm;
    float* Wk = sm + SM_X;          // later reused as ks[512][17]
    float* Wv = Wk + SM_W;          // later reused as vs[512][18]
    float* ks = Wk;
    float* vs = Wv;
    float* pkv = sm;                // 256 ull (aliases XsT area, used post-reduction)
    float* psum = sm + 512;         // 32 floats
    int tid = threadIdx.x, lane = tid & 31, cg = tid >> 5, g0 = blockIdx.x * 64;
    load_X_T(XsT, X, g0, tid);
    load_W(Wk, g_WT + 16384, tid);
    load_W(Wv, g_WT + 32768, tid);
    __syncthreads();

    ull acc[2][8];
    gemm_main(XsT, Wk, lane, cg, acc);
    float t = (float)((g0 >> 10) & 7);
    float kc[2][16];
#pragma unroll
    for (int i = 0; i < 2; ++i) {
        unpack16(acc[i], bk, cg, kc[i]);
        rope16(kc[i], t);
        softmax16(kc[i]);
    }
    gemm_main(XsT, Wv, lane, cg, acc);   // acc now = v (bias below)
    __syncthreads();                     // all gemm reads of Wk/Wv/XsT done
#pragma unroll
    for (int i = 0; i < 2; ++i) {
        int s = (lane + 32 * i) * 8 + cg;
        float vc[16];
        unpack16(acc[i], bv, cg, vc);
#pragma unroll
        for (int e = 0; e < 16; ++e) { ks[s * 17 + e] = kc[i][e]; vs[s * 18 + e] = vc[e]; }
    }
    __syncthreads();

    // thread (d, ep, half): partial over 256 s values; f32x2 over col pair (2ep,2ep+1)
    int d = tid & 15, ep = (tid >> 4) & 7, half = tid >> 7;
    ull a2 = 0ULL; float sk = 0.f;
    int s0 = half * 256;
#pragma unroll 4
    for (int s = s0; s < s0 + 256; ++s) {
        float kd = ks[s * 17 + d];
        ffma2(a2, bcast2(kd), *(const ull*)(vs + s * 18 + 2 * ep));
        if (ep == 0) sk += kd;
    }
    __syncthreads();                     // ks/vs reads done before pkv/psum overwrite aliased sm
    ((ull*)pkv)[tid] = a2;
    if (ep == 0) psum[half * 16 + d] = sk;
    __syncthreads();
    float* out = g_part + (size_t)blockIdx.x * 272;
    if (tid < 128) {
        float a, b, c, e2;
        unpk2(((ull*)pkv)[tid], a, b);
        unpk2(((ull*)pkv)[tid + 128], c, e2);
        int dd = tid & 15, pp = tid >> 4;
        out[dd * 16 + 2 * pp] = a + c;
        out[dd * 16 + 2 * pp + 1] = b + e2;
    }
    if (tid < 16) out[256 + tid] = psum[tid] + psum[16 + tid];
}

__global__ void k_kvreduce() {
    int bh = blockIdx.x, t = threadIdx.x;
    float s = 0.f;
    for (int i = 0; i < 128; ++i) s += g_part[(size_t)(bh * 128 + i) * 272 + t];
    g_kv[bh * 272 + t] = s;
}

// out = q + (q@kv)*Dinv, per 16-chunk, in place in g_q
__global__ void __launch_bounds__(256, 4) k_attn() {
    __shared__ __align__(16) float kv[272];
    int tid = threadIdx.x, g0 = blockIdx.x * 64, bh = g0 >> 11;
    for (int i = tid; i < 272; i += 256) kv[i] = g_kv[bh * 272 + i];  // full 272
    __syncthreads();
#pragma unroll
    for (int it = 0; it < 2; ++it) {
        int cc = tid + 256 * it, row = cc >> 3, j = cc & 7;
        float* qp = g_q + (size_t)(g0 + row) * 128 + j * 16;
        float q[16];
#pragma unroll
        for (int p = 0; p < 4; ++p) {
            float4 x = *(const float4*)(qp + 4 * p);
            q[4 * p] = x.x; q[4 * p + 1] = x.y; q[4 * p + 2] = x.z; q[4 * p + 3] = x.w;
        }
        float den = 0.f;
#pragma unroll
        for (int d = 0; d < 16; ++d) den += q[d] * kv[256 + d];
        float Dinv = 1.0f / fmaxf(den, 1e-8f);
        ull o2[8];
#pragma unroll
        for (int p = 0; p < 8; ++p) o2[p] = 0ULL;
#pragma unroll
        for (int d = 0; d < 16; ++d) {
            ull qd = bcast2(q[d]);
            const ull* kr = (const ull*)(kv + d * 16);
#pragma unroll
            for (int p = 0; p < 8; ++p) ffma2(o2[p], qd, kr[p]);
        }
        float r[16];
#pragma unroll
        for (int p = 0; p < 8; ++p) {
            float lo, hi; unpk2(o2[p], lo, hi);
            r[2 * p] = q[2 * p] + lo * Dinv;
            r[2 * p + 1] = q[2 * p + 1] + hi * Dinv;
        }
        store16(qp, r);
    }
}

// final: gather (head transpose) @ WoT + bo -> d_out (flat layout matches)
__global__ void __launch_bounds__(256, 2) k_out(const float* __restrict__ bias,
                                                float* __restrict__ out) {
    extern __shared__ float sm[];
    float* XsT = sm; float* Ws = sm + SM_X;
    int tid = threadIdx.x, lane = tid & 31, cg = tid >> 5, g0 = blockIdx.x * 64;
#pragma unroll
    for (int rep = 0; rep < 8; ++rep) {
        int i4 = tid + rep * 256, r = i4 >> 5, c4 = i4 & 31;
        int m = g0 + r, s = m & 16383, base = m & ~16383;
        int src = base + (c4 >> 2) * 2048 + (s >> 3);
        float4 v = *(const float4*)(g_q + (size_t)src * 128 + (s & 7) * 16 + (c4 & 3) * 4);
        XsT[(c4 * 4 + 0) * LDXT + r] = v.x;
        XsT[(c4 * 4 + 1) * LDXT + r] = v.y;
        XsT[(c4 * 4 + 2) * LDXT + r] = v.z;
        XsT[(c4 * 4 + 3) * LDXT + r] = v.w;
    }
    load_W(Ws, g_WT + 49152, tid);
    __syncthreads();
    ull acc[2][8];
    gemm_main(XsT, Ws, lane, cg, acc);
#pragma unroll
    for (int i = 0; i < 2; ++i) {
        int g = g0 + lane + 32 * i;
        float v[16];
        unpack16(acc[i], bias, cg, v);
        store16(out + (size_t)g * 128 + cg * 16, v);
    }
}

extern "C" void kernel_launch(void* const* d_in, const int* in_sizes, int n_in,
                              void* d_out, int out_size) {
    const float* edge = (const float*)d_in[1];
    const float* qdat = (const float*)d_in[2];
    const float* Wq = (const float*)d_in[3];
    const float* bq = (const float*)d_in[4];
    const float* Wk1 = (const float*)d_in[9];
    const float* bk1 = (const float*)d_in[10];
    const float* Wv1 = (const float*)d_in[11];
    const float* bv1 = (const float*)d_in[12];
    const float* Wo = (const float*)d_in[13];
    const float* bo = (const float*)d_in[14];

    int smQ = (SM_X + SM_W) * 4;          // 104448
    int smKV = (SM_X + 2 * SM_W) * 4;     // 172032
    cudaFuncSetAttribute(k_qproj, cudaFuncAttributeMaxDynamicSharedMemorySize, smQ);
    cudaFuncSetAttribute(k_kv, cudaFuncAttributeMaxDynamicSharedMemorySize, smKV);
    cudaFuncSetAttribute(k_out, cudaFuncAttributeMaxDynamicSharedMemorySize, smQ);

    k_wtrans<<<4, 256>>>(Wq, Wk1, Wv1, Wo);
    k_qproj<<<1024, 256, smQ>>>(qdat, bq);
    k_kv<<<4096, 256, smKV>>>(edge, bk1, bv1);
    k_kvreduce<<<32, 272>>>();
    k_attn<<<1024, 256>>>();
    k_out<<<1024, 256, smQ>>>(bo, (float*)d_out);
}

// round 7
// speedup vs baseline: 2.1429x; 1.0511x over previous
#include <cuda_runtime.h>

typedef unsigned long long ull;
typedef unsigned int uint;

// Shapes: B_T=32,N=2048,E=8192,D=128,T=8,H=8,dh=16,B=4
// q rows 65536, k/v rows 262144 (edge branch only; x_0 branch is dead code).

__device__ float g_q[65536 * 128];     // q (softmax+rope), then attn output in place
__device__ float g_WT[4 * 16384];      // WqT, Wk1T, Wv1T, WoT ; WT[k*128+c]=W[c*128+k]
__device__ float g_part[4096 * 272];   // per-block kv partials (256 kv + 16 ksum)
__device__ float g_kv[32 * 272];       // reduced per (b,h)

static __device__ __forceinline__ ull bcast2(float x) {
    ull r; asm("mov.b64 %0, {%1, %1};" : "=l"(r) : "r"(__float_as_uint(x))); return r;
}
static __device__ __forceinline__ void ffma2(ull& a, ull x, ull y) {
    asm("fma.rn.f32x2 %0, %1, %2, %0;" : "+l"(a) : "l"(x), "l"(y));
}
static __device__ __forceinline__ void unpk2(ull v, float& lo, float& hi) {
    uint l, h; asm("mov.b64 {%0, %1}, %2;" : "=r"(l), "=r"(h) : "l"(v));
    lo = __uint_as_float(l); hi = __uint_as_float(h);
}

#define LDW 132            // padded W row (floats)
#define LDXT 72            // padded XsT row (floats)
#define SM_X (128 * LDXT)  // 9216 floats
#define SM_W (128 * LDW)   // 16896 floats

// XsT[k*LDXT + r] = X[g0+r][k]
static __device__ __forceinline__ void load_X_T(float* XsT, const float* __restrict__ X,
                                                int g0, int tid) {
#pragma unroll
    for (int rep = 0; rep < 8; ++rep) {
        int i4 = tid + rep * 256, r = i4 >> 5, c4 = i4 & 31;
        float4 v = *(const float4*)(X + (size_t)(g0 + r) * 128 + c4 * 4);
        XsT[(c4 * 4 + 0) * LDXT + r] = v.x;
        XsT[(c4 * 4 + 1) * LDXT + r] = v.y;
        XsT[(c4 * 4 + 2) * LDXT + r] = v.z;
        XsT[(c4 * 4 + 3) * LDXT + r] = v.w;
    }
}
static __device__ __forceinline__ void load_W(float* Ws, const float* __restrict__ src, int tid) {
#pragma unroll
    for (int rep = 0; rep < 16; ++rep) {
        int i4 = tid + rep * 256, k = i4 >> 5, c4 = i4 & 31;
        *(float4*)(Ws + k * LDW + c4 * 4) = *(const float4*)(src + k * 128 + c4 * 4);
    }
}

// 256 thr: warp cg=tid>>5 -> cols [cg*16,+16); lane -> rows {lane, lane+32}
// acc[i][p] packs cols (cg*16+2p, cg*16+2p+1) for row lane+32*i.
// W strip read as ulonglong2 (LDS.128, warp-broadcast).
static __device__ __forceinline__ void gemm_main(const float* XsT, const float* Ws,
                                                 int lane, int cg, ull acc[2][8]) {
#pragma unroll
    for (int i = 0; i < 2; ++i)
#pragma unroll
        for (int p = 0; p < 8; ++p) acc[i][p] = 0ULL;
#pragma unroll 4
    for (int k = 0; k < 128; ++k) {
        ull x0 = bcast2(XsT[k * LDXT + lane]);
        ull x1 = bcast2(XsT[k * LDXT + lane + 32]);
        const ulonglong2* w = (const ulonglong2*)(Ws + k * LDW + cg * 16);
#pragma unroll
        for (int q = 0; q < 4; ++q) {
            ulonglong2 wp = w[q];
            ffma2(acc[0][2 * q], x0, wp.x);
            ffma2(acc[0][2 * q + 1], x0, wp.y);
            ffma2(acc[1][2 * q], x1, wp.x);
            ffma2(acc[1][2 * q + 1], x1, wp.y);
        }
    }
}

static __device__ __forceinline__ void unpack16(const ull a[8], const float* __restrict__ bias,
                                                int cg, float v[16]) {
#pragma unroll
    for (int p = 0; p < 8; ++p) {
        float lo, hi; unpk2(a[p], lo, hi);
        v[2 * p] = lo + bias[cg * 16 + 2 * p];
        v[2 * p + 1] = hi + bias[cg * 16 + 2 * p + 1];
    }
}
static __device__ __forceinline__ void softmax16(float v[16]) {
    float m = v[0];
#pragma unroll
    for (int e = 1; e < 16; ++e) m = fmaxf(m, v[e]);
    float s = 0.f;
#pragma unroll
    for (int e = 0; e < 16; ++e) { v[e] = __expf(v[e] - m); s += v[e]; }
    float inv = 1.0f / s;
#pragma unroll
    for (int e = 0; e < 16; ++e) v[e] *= inv;
}
static __device__ __forceinline__ void rope16(float v[16], float t) {
    const float F[8] = {1.0f, 0.31622776601683794f, 0.1f, 0.031622776601683794f,
                        0.01f, 0.0031622776601683794f, 0.001f, 0.00031622776601683794f};
#pragma unroll
    for (int p = 0; p < 8; ++p) {
        float sn, cs; __sincosf(t * F[p], &sn, &cs);
        float a = v[2 * p], b = v[2 * p + 1];
        v[2 * p] = a * cs - b * sn;
        v[2 * p + 1] = a * sn + b * cs;
    }
}
static __device__ __forceinline__ void store16(float* p, const float v[16]) {
#pragma unroll
    for (int q = 0; q < 4; ++q)
        *(float4*)(p + 4 * q) = make_float4(v[4 * q], v[4 * q + 1], v[4 * q + 2], v[4 * q + 3]);
}

__global__ void k_wtrans(const float* __restrict__ w0, const float* __restrict__ w1,
                         const float* __restrict__ w2, const float* __restrict__ w3) {
    const float* s = blockIdx.x == 0 ? w0 : blockIdx.x == 1 ? w1 : blockIdx.x == 2 ? w2 : w3;
    float* d = g_WT + blockIdx.x * 16384;
    for (int i = threadIdx.x; i < 16384; i += 256) d[i] = s[(i & 127) * 128 + (i >> 7)];
}

// q = rope(softmax(q_data@WqT+bq))   rope-t = (g>>8)&7
__global__ void __launch_bounds__(256, 2) k_qproj(const float* __restrict__ X,
                                                  const float* __restrict__ bias) {
    extern __shared__ float sm[];
    float* XsT = sm; float* Ws = sm + SM_X;
    int tid = threadIdx.x, lane = tid & 31, cg = tid >> 5, g0 = blockIdx.x * 64;
    load_X_T(XsT, X, g0, tid);
    load_W(Ws, g_WT, tid);
    __syncthreads();
    ull acc[2][8];
    gemm_main(XsT, Ws, lane, cg, acc);
#pragma unroll
    for (int i = 0; i < 2; ++i) {
        int g = g0 + lane + 32 * i;
        float v[16];
        unpack16(acc[i], bias, cg, v);
        softmax16(v);
        rope16(v, (float)((g >> 8) & 7));
        store16(g_q + (size_t)g * 128 + cg * 16, v);
    }
}

// fused K/V projection + softmax(rope(k)) + block-local kv/ksum reduction.
// Single W buffer (Wk then Wv reloaded) -> smem 104KB -> occupancy 2.
__global__ void __launch_bounds__(256, 2) k_kv(const float* __restrict__ X,
                                               const float* __restrict__ bk,
                                               const float* __restrict__ bv) {
    extern __shared__ float sm[];
    float* XsT = sm;               // [SM_X]
    float* Wbuf = sm + SM_X;       // [SM_W], Wk then Wv
    float* ks = sm;                // 512*17 = 8704 floats (aliases XsT, post-GEMM)
    float* vs = sm + 8704;         // 512*18 = 9216 floats (spills into Wbuf area)
    float* pkv = sm + 17920;       // 256 ull = 512 floats (disjoint from ks/vs)
    float* psum = sm + 18432;      // 32 floats
    int tid = threadIdx.x, lane = tid & 31, cg = tid >> 5, g0 = blockIdx.x * 64;
    load_X_T(XsT, X, g0, tid);
    load_W(Wbuf, g_WT + 16384, tid);     // Wk
    __syncthreads();

    ull acc[2][8];
    gemm_main(XsT, Wbuf, lane, cg, acc);
    float t = (float)((g0 >> 10) & 7);
    float kc[2][16];
#pragma unroll
    for (int i = 0; i < 2; ++i) {
        unpack16(acc[i], bk, cg, kc[i]);
        rope16(kc[i], t);
        softmax16(kc[i]);
    }
    __syncthreads();                     // Wk reads done
    load_W(Wbuf, g_WT + 32768, tid);     // Wv
    __syncthreads();
    gemm_main(XsT, Wbuf, lane, cg, acc); // acc = v (bias below)
    __syncthreads();                     // XsT/Wbuf reads done before ks/vs overwrite
#pragma unroll
    for (int i = 0; i < 2; ++i) {
        int s = (lane + 32 * i) * 8 + cg;
        float vc[16];
        unpack16(acc[i], bv, cg, vc);
#pragma unroll
        for (int e = 0; e < 16; ++e) { ks[s * 17 + e] = kc[i][e]; vs[s * 18 + e] = vc[e]; }
    }
    __syncthreads();

    // thread (d, ep, half): partial over 256 s values; f32x2 over col pair (2ep,2ep+1)
    int d = tid & 15, ep = (tid >> 4) & 7, half = tid >> 7;
    ull a2 = 0ULL; float sk = 0.f;
    int s0 = half * 256;
#pragma unroll 8
    for (int s = s0; s < s0 + 256; ++s) {
        float kd = ks[s * 17 + d];
        ffma2(a2, bcast2(kd), *(const ull*)(vs + s * 18 + 2 * ep));
        if (ep == 0) sk += kd;
    }
    ((ull*)pkv)[tid] = a2;               // pkv/psum disjoint from ks/vs: no sync needed
    if (ep == 0) psum[half * 16 + d] = sk;
    __syncthreads();
    float* out = g_part + (size_t)blockIdx.x * 272;
    if (tid < 128) {
        float a, b, c, e2;
        unpk2(((ull*)pkv)[tid], a, b);
        unpk2(((ull*)pkv)[tid + 128], c, e2);
        int dd = tid & 15, pp = tid >> 4;
        out[dd * 16 + 2 * pp] = a + c;
        out[dd * 16 + 2 * pp + 1] = b + e2;
    }
    if (tid < 16) out[256 + tid] = psum[tid] + psum[16 + tid];
}

__global__ void k_kvreduce() {
    int bh = blockIdx.x, t = threadIdx.x;
    float s = 0.f;
    for (int i = 0; i < 128; ++i) s += g_part[(size_t)(bh * 128 + i) * 272 + t];
    g_kv[bh * 272 + t] = s;
}

// out = q + (q@kv)*Dinv, per 16-chunk, in place in g_q
__global__ void __launch_bounds__(256, 4) k_attn() {
    __shared__ __align__(16) float kv[272];
    int tid = threadIdx.x, g0 = blockIdx.x * 64, bh = g0 >> 11;
    for (int i = tid; i < 272; i += 256) kv[i] = g_kv[bh * 272 + i];
    __syncthreads();
#pragma unroll
    for (int it = 0; it < 2; ++it) {
        int cc = tid + 256 * it, row = cc >> 3, j = cc & 7;
        float* qp = g_q + (size_t)(g0 + row) * 128 + j * 16;
        float q[16];
#pragma unroll
        for (int p = 0; p < 4; ++p) {
            float4 x = *(const float4*)(qp + 4 * p);
            q[4 * p] = x.x; q[4 * p + 1] = x.y; q[4 * p + 2] = x.z; q[4 * p + 3] = x.w;
        }
        float den = 0.f;
#pragma unroll
        for (int d = 0; d < 16; ++d) den += q[d] * kv[256 + d];
        float Dinv = 1.0f / fmaxf(den, 1e-8f);
        ull o2[8];
#pragma unroll
        for (int p = 0; p < 8; ++p) o2[p] = 0ULL;
#pragma unroll
        for (int d = 0; d < 16; ++d) {
            ull qd = bcast2(q[d]);
            const ull* kr = (const ull*)(kv + d * 16);
#pragma unroll
            for (int p = 0; p < 8; ++p) ffma2(o2[p], qd, kr[p]);
        }
        float r[16];
#pragma unroll
        for (int p = 0; p < 8; ++p) {
            float lo, hi; unpk2(o2[p], lo, hi);
            r[2 * p] = q[2 * p] + lo * Dinv;
            r[2 * p + 1] = q[2 * p + 1] + hi * Dinv;
        }
        store16(qp, r);
    }
}

// final: gather (head transpose) @ WoT + bo -> d_out (flat layout matches)
__global__ void __launch_bounds__(256, 2) k_out(const float* __restrict__ bias,
                                                float* __restrict__ out) {
    extern __shared__ float sm[];
    float* XsT = sm; float* Ws = sm + SM_X;
    int tid = threadIdx.x, lane = tid & 31, cg = tid >> 5, g0 = blockIdx.x * 64;
#pragma unroll
    for (int rep = 0; rep < 8; ++rep) {
        int i4 = tid + rep * 256, r = i4 >> 5, c4 = i4 & 31;
        int m = g0 + r, s = m & 16383, base = m & ~16383;
        int src = base + (c4 >> 2) * 2048 + (s >> 3);
        float4 v = *(const float4*)(g_q + (size_t)src * 128 + (s & 7) * 16 + (c4 & 3) * 4);
        XsT[(c4 * 4 + 0) * LDXT + r] = v.x;
        XsT[(c4 * 4 + 1) * LDXT + r] = v.y;
        XsT[(c4 * 4 + 2) * LDXT + r] = v.z;
        XsT[(c4 * 4 + 3) * LDXT + r] = v.w;
    }
    load_W(Ws, g_WT + 49152, tid);
    __syncthreads();
    ull acc[2][8];
    gemm_main(XsT, Ws, lane, cg, acc);
#pragma unroll
    for (int i = 0; i < 2; ++i) {
        int g = g0 + lane + 32 * i;
        float v[16];
        unpack16(acc[i], bias, cg, v);
        store16(out + (size_t)g * 128 + cg * 16, v);
    }
}

extern "C" void kernel_launch(void* const* d_in, const int* in_sizes, int n_in,
                              void* d_out, int out_size) {
    const float* edge = (const float*)d_in[1];
    const float* qdat = (const float*)d_in[2];
    const float* Wq = (const float*)d_in[3];
    const float* bq = (const float*)d_in[4];
    const float* Wk1 = (const float*)d_in[9];
    const float* bk1 = (const float*)d_in[10];
    const float* Wv1 = (const float*)d_in[11];
    const float* bv1 = (const float*)d_in[12];
    const float* Wo = (const float*)d_in[13];
    const float* bo = (const float*)d_in[14];

    int smQ = (SM_X + SM_W) * 4;   // 104448 bytes (also k_kv now)
    cudaFuncSetAttribute(k_qproj, cudaFuncAttributeMaxDynamicSharedMemorySize, smQ);
    cudaFuncSetAttribute(k_kv, cudaFuncAttributeMaxDynamicSharedMemorySize, smQ);
    cudaFuncSetAttribute(k_out, cudaFuncAttributeMaxDynamicSharedMemorySize, smQ);

    k_wtrans<<<4, 256>>>(Wq, Wk1, Wv1, Wo);
    k_qproj<<<1024, 256, smQ>>>(qdat, bq);
    k_kv<<<4096, 256, smQ>>>(edge, bk1, bv1);
    k_kvreduce<<<32, 272>>>();
    k_attn<<<1024, 256>>>();
    k_out<<<1024, 256, smQ>>>(bo, (float*)d_out);
}

// round 9
// speedup vs baseline: 2.1577x; 1.0069x over previous
#include <cuda_runtime.h>

typedef unsigned long long ull;
typedef unsigned int uint;

// Shapes: B_T=32,N=2048,E=8192,D=128,T=8,H=8,dh=16,B=4
// q rows 65536, k/v rows 262144 (edge branch only; x_0 branch is dead code).

__device__ float g_q[65536 * 128];     // q (softmax+rope); attn applied on the fly in k_out
__device__ float g_WT[4 * 16384];      // WqT, Wk1T, Wv1T, WoT ; WT[k*128+c]=W[c*128+k]
__device__ float g_part[4096 * 272];   // per-block kv partials (256 kv + 16 ksum)
__device__ float g_kv[32 * 272];       // reduced per (b,h)

static __device__ __forceinline__ ull bcast2(float x) {
    ull r; asm("mov.b64 %0, {%1, %1};" : "=l"(r) : "r"(__float_as_uint(x))); return r;
}
static __device__ __forceinline__ void ffma2(ull& a, ull x, ull y) {
    asm("fma.rn.f32x2 %0, %1, %2, %0;" : "+l"(a) : "l"(x), "l"(y));
}
static __device__ __forceinline__ void unpk2(ull v, float& lo, float& hi) {
    uint l, h; asm("mov.b64 {%0, %1}, %2;" : "=r"(l), "=r"(h) : "l"(v));
    lo = __uint_as_float(l); hi = __uint_as_float(h);
}

#define LDW 132            // padded W row (floats)
#define LDXT 72            // padded XsT row (floats)
#define SM_X (128 * LDXT)  // 9216 floats
#define SM_W (128 * LDW)   // 16896 floats

// XsT[k*LDXT + r] = X[g0+r][k]
static __device__ __forceinline__ void load_X_T(float* XsT, const float* __restrict__ X,
                                                int g0, int tid) {
#pragma unroll
    for (int rep = 0; rep < 8; ++rep) {
        int i4 = tid + rep * 256, r = i4 >> 5, c4 = i4 & 31;
        float4 v = *(const float4*)(X + (size_t)(g0 + r) * 128 + c4 * 4);
        XsT[(c4 * 4 + 0) * LDXT + r] = v.x;
        XsT[(c4 * 4 + 1) * LDXT + r] = v.y;
        XsT[(c4 * 4 + 2) * LDXT + r] = v.z;
        XsT[(c4 * 4 + 3) * LDXT + r] = v.w;
    }
}
static __device__ __forceinline__ void load_W(float* Ws, const float* __restrict__ src, int tid) {
#pragma unroll
    for (int rep = 0; rep < 16; ++rep) {
        int i4 = tid + rep * 256, k = i4 >> 5, c4 = i4 & 31;
        *(float4*)(Ws + k * LDW + c4 * 4) = *(const float4*)(src + k * 128 + c4 * 4);
    }
}

// 256 thr: warp cg=tid>>5 -> cols [cg*16,+16); lane -> rows {lane, lane+32}
// acc[i][p] packs cols (cg*16+2p, cg*16+2p+1) for row lane+32*i.
static __device__ __forceinline__ void gemm_main(const float* XsT, const float* Ws,
                                                 int lane, int cg, ull acc[2][8]) {
#pragma unroll
    for (int i = 0; i < 2; ++i)
#pragma unroll
        for (int p = 0; p < 8; ++p) acc[i][p] = 0ULL;
#pragma unroll 4
    for (int k = 0; k < 128; ++k) {
        ull x0 = bcast2(XsT[k * LDXT + lane]);
        ull x1 = bcast2(XsT[k * LDXT + lane + 32]);
        const ulonglong2* w = (const ulonglong2*)(Ws + k * LDW + cg * 16);
#pragma unroll
        for (int q = 0; q < 4; ++q) {
            ulonglong2 wp = w[q];
            ffma2(acc[0][2 * q], x0, wp.x);
            ffma2(acc[0][2 * q + 1], x0, wp.y);
            ffma2(acc[1][2 * q], x1, wp.x);
            ffma2(acc[1][2 * q + 1], x1, wp.y);
        }
    }
}

static __device__ __forceinline__ void unpack16(const ull a[8], const float* __restrict__ bias,
                                                int cg, float v[16]) {
#pragma unroll
    for (int p = 0; p < 8; ++p) {
        float lo, hi; unpk2(a[p], lo, hi);
        v[2 * p] = lo + bias[cg * 16 + 2 * p];
        v[2 * p + 1] = hi + bias[cg * 16 + 2 * p + 1];
    }
}
static __device__ __forceinline__ void softmax16(float v[16]) {
    float m = v[0];
#pragma unroll
    for (int e = 1; e < 16; ++e) m = fmaxf(m, v[e]);
    float s = 0.f;
#pragma unroll
    for (int e = 0; e < 16; ++e) { v[e] = __expf(v[e] - m); s += v[e]; }
    float inv = 1.0f / s;
#pragma unroll
    for (int e = 0; e < 16; ++e) v[e] *= inv;
}
static __device__ __forceinline__ void rope16(float v[16], float t) {
    const float F[8] = {1.0f, 0.31622776601683794f, 0.1f, 0.031622776601683794f,
                        0.01f, 0.0031622776601683794f, 0.001f, 0.00031622776601683794f};
#pragma unroll
    for (int p = 0; p < 8; ++p) {
        float sn, cs; __sincosf(t * F[p], &sn, &cs);
        float a = v[2 * p], b = v[2 * p + 1];
        v[2 * p] = a * cs - b * sn;
        v[2 * p + 1] = a * sn + b * cs;
    }
}
static __device__ __forceinline__ void store16(float* p, const float v[16]) {
#pragma unroll
    for (int q = 0; q < 4; ++q)
        *(float4*)(p + 4 * q) = make_float4(v[4 * q], v[4 * q + 1], v[4 * q + 2], v[4 * q + 3]);
}

__global__ void k_wtrans(const float* __restrict__ w0, const float* __restrict__ w1,
                         const float* __restrict__ w2, const float* __restrict__ w3) {
    const float* s = blockIdx.x == 0 ? w0 : blockIdx.x == 1 ? w1 : blockIdx.x == 2 ? w2 : w3;
    float* d = g_WT + blockIdx.x * 16384;
    for (int i = threadIdx.x; i < 16384; i += 256) d[i] = s[(i & 127) * 128 + (i >> 7)];
}

// q = rope(softmax(q_data@WqT+bq))   rope-t = (g>>8)&7
__global__ void __launch_bounds__(256, 2) k_qproj(const float* __restrict__ X,
                                                  const float* __restrict__ bias) {
    extern __shared__ float sm[];
    float* XsT = sm; float* Ws = sm + SM_X;
    int tid = threadIdx.x, lane = tid & 31, cg = tid >> 5, g0 = blockIdx.x * 64;
    load_X_T(XsT, X, g0, tid);
    load_W(Ws, g_WT, tid);
    __syncthreads();
    ull acc[2][8];
    gemm_main(XsT, Ws, lane, cg, acc);
#pragma unroll
    for (int i = 0; i < 2; ++i) {
        int g = g0 + lane + 32 * i;
        float v[16];
        unpack16(acc[i], bias, cg, v);
        softmax16(v);
        rope16(v, (float)((g >> 8) & 7));
        store16(g_q + (size_t)g * 128 + cg * 16, v);
    }
}

// fused K/V projection + softmax(rope(k)) + block-local kv/ksum reduction.
// Single W buffer (Wk then Wv reloaded) -> smem 104KB -> occupancy 2.
// boff: block-index offset (grid is split across two launches for profiling).
__global__ void __launch_bounds__(256, 2) k_kv(const float* __restrict__ X,
                                               const float* __restrict__ bk,
                                               const float* __restrict__ bv, int boff) {
    extern __shared__ float sm[];
    float* XsT = sm;               // [SM_X]
    float* Wbuf = sm + SM_X;       // [SM_W], Wk then Wv
    float* ks = sm;                // 512*17 = 8704 floats (aliases XsT, post-GEMM)
    float* vs = sm + 8704;         // 512*18 = 9216 floats (spills into Wbuf area)
    float* pkv = sm + 17920;       // 256 ull = 512 floats (disjoint from ks/vs)
    float* psum = sm + 18432;      // 32 floats
    int tid = threadIdx.x, lane = tid & 31, cg = tid >> 5;
    int blk = blockIdx.x + boff, g0 = blk * 64;
    load_X_T(XsT, X, g0, tid);
    load_W(Wbuf, g_WT + 16384, tid);     // Wk
    __syncthreads();

    ull acc[2][8];
    gemm_main(XsT, Wbuf, lane, cg, acc);
    float t = (float)((g0 >> 10) & 7);
    float kc[2][16];
#pragma unroll
    for (int i = 0; i < 2; ++i) {
        unpack16(acc[i], bk, cg, kc[i]);
        rope16(kc[i], t);
        softmax16(kc[i]);
    }
    __syncthreads();                     // Wk reads done
    load_W(Wbuf, g_WT + 32768, tid);     // Wv
    __syncthreads();
    gemm_main(XsT, Wbuf, lane, cg, acc); // acc = v (bias below)
    __syncthreads();                     // XsT/Wbuf reads done before ks/vs overwrite
#pragma unroll
    for (int i = 0; i < 2; ++i) {
        int s = (lane + 32 * i) * 8 + cg;
        float vc[16];
        unpack16(acc[i], bv, cg, vc);
#pragma unroll
        for (int e = 0; e < 16; ++e) { ks[s * 17 + e] = kc[i][e]; vs[s * 18 + e] = vc[e]; }
    }
    __syncthreads();

    // thread (d, ep, half): partial over 256 s values; f32x2 over col pair (2ep,2ep+1)
    int d = tid & 15, ep = (tid >> 4) & 7, half = tid >> 7;
    ull a2 = 0ULL; float sk = 0.f;
    int s0 = half * 256;
#pragma unroll 8
    for (int s = s0; s < s0 + 256; ++s) {
        float kd = ks[s * 17 + d];
        ffma2(a2, bcast2(kd), *(const ull*)(vs + s * 18 + 2 * ep));
        if (ep == 0) sk += kd;
    }
    ((ull*)pkv)[tid] = a2;               // pkv/psum disjoint from ks/vs: no sync needed
    if (ep == 0) psum[half * 16 + d] = sk;
    __syncthreads();
    float* out = g_part + (size_t)blk * 272;
    if (tid < 128) {
        float a, b, c, e2;
        unpk2(((ull*)pkv)[tid], a, b);
        unpk2(((ull*)pkv)[tid + 128], c, e2);
        int dd = tid & 15, pp = tid >> 4;
        out[dd * 16 + 2 * pp] = a + c;
        out[dd * 16 + 2 * pp + 1] = b + e2;
    }
    if (tid < 16) out[256 + tid] = psum[tid] + psum[16 + tid];
}

__global__ void k_kvreduce() {
    int bh = blockIdx.x, t = threadIdx.x;
    float s = 0.f;
    for (int i = 0; i < 128; ++i) s += g_part[(size_t)(bh * 128 + i) * 272 + t];
    g_kv[bh * 272 + t] = s;
}

// final: gather (head transpose) with fused attention epilogue, @ WoT + bo -> d_out.
// For each gathered 16-chunk: o = q + (q @ kv_h) * Dinv, Dinv = 1/max(q.ksum_h,1e-8).
__global__ void __launch_bounds__(256, 2) k_out(const float* __restrict__ bias,
                                                float* __restrict__ out) {
    extern __shared__ float sm[];
    float* XsT = sm;                 // SM_X
    float* Ws = sm + SM_X;           // SM_W
    float* kvs = sm + SM_X + SM_W;   // 8*272 floats (kv tables for this batch)
    int tid = threadIdx.x, lane = tid & 31, cg = tid >> 5, g0 = blockIdx.x * 64;
    int b = g0 >> 14;                // batch (constant within block)
    load_W(Ws, g_WT + 49152, tid);
    for (int i = tid; i < 8 * 272; i += 256) kvs[i] = g_kv[b * 8 * 272 + i];
    __syncthreads();
    // gather + attention: 512 chunks (64 rows x 8 heads), 2 per thread
#pragma unroll
    for (int it = 0; it < 2; ++it) {
        int cc = tid + 256 * it, r = cc >> 3, h = cc & 7;
        int m = g0 + r, s = m & 16383;
        int src = (m & ~16383) + h * 2048 + (s >> 3);
        const float* qp = g_q + (size_t)src * 128 + (s & 7) * 16;
        const float* kv = kvs + h * 272;
        float q[16];
#pragma unroll
        for (int p = 0; p < 4; ++p) {
            float4 x = *(const float4*)(qp + 4 * p);
            q[4 * p] = x.x; q[4 * p + 1] = x.y; q[4 * p + 2] = x.z; q[4 * p + 3] = x.w;
        }
        float den = 0.f;
#pragma unroll
        for (int d = 0; d < 16; ++d) den += q[d] * kv[256 + d];
        float Dinv = 1.0f / fmaxf(den, 1e-8f);
        ull o2[8];
#pragma unroll
        for (int p = 0; p < 8; ++p) o2[p] = 0ULL;
#pragma unroll
        for (int d = 0; d < 16; ++d) {
            ull qd = bcast2(q[d]);
            const ull* kr = (const ull*)(kv + d * 16);
#pragma unroll
            for (int p = 0; p < 8; ++p) ffma2(o2[p], qd, kr[p]);
        }
#pragma unroll
        for (int p = 0; p < 8; ++p) {
            float lo, hi; unpk2(o2[p], lo, hi);
            XsT[(h * 16 + 2 * p) * LDXT + r] = q[2 * p] + lo * Dinv;
            XsT[(h * 16 + 2 * p + 1) * LDXT + r] = q[2 * p + 1] + hi * Dinv;
        }
    }
    __syncthreads();
    ull acc[2][8];
    gemm_main(XsT, Ws, lane, cg, acc);
#pragma unroll
    for (int i = 0; i < 2; ++i) {
        int g = g0 + lane + 32 * i;
        float v[16];
        unpack16(acc[i], bias, cg, v);
        store16(out + (size_t)g * 128 + cg * 16, v);
    }
}

extern "C" void kernel_launch(void* const* d_in, const int* in_sizes, int n_in,
                              void* d_out, int out_size) {
    const float* edge = (const float*)d_in[1];
    const float* qdat = (const float*)d_in[2];
    const float* Wq = (const float*)d_in[3];
    const float* bq = (const float*)d_in[4];
    const float* Wk1 = (const float*)d_in[9];
    const float* bk1 = (const float*)d_in[10];
    const float* Wv1 = (const float*)d_in[11];
    const float* bv1 = (const float*)d_in[12];
    const float* Wo = (const float*)d_in[13];
    const float* bo = (const float*)d_in[14];

    int smQ = (SM_X + SM_W) * 4;               // 104448 bytes
    int smO = (SM_X + SM_W + 8 * 272) * 4;     // 113152 bytes
    cudaFuncSetAttribute(k_qproj, cudaFuncAttributeMaxDynamicSharedMemorySize, smQ);
    cudaFuncSetAttribute(k_kv, cudaFuncAttributeMaxDynamicSharedMemorySize, smQ);
    cudaFuncSetAttribute(k_out, cudaFuncAttributeMaxDynamicSharedMemorySize, smO);

    k_wtrans<<<4, 256>>>(Wq, Wk1, Wv1, Wo);
    k_qproj<<<1024, 256, smQ>>>(qdat, bq);
    k_kv<<<2048, 256, smQ>>>(edge, bk1, bv1, 0);      // first half
    k_kv<<<2048, 256, smQ>>>(edge, bk1, bv1, 2048);   // second half (profiled slot)
    k_kvreduce<<<32, 272>>>();
    k_out<<<1024, 256, smO>>>(bo, (float*)d_out);
}